// round 2
// baseline (speedup 1.0000x reference)
#include <cuda_runtime.h>
#include <cstdint>

#define NN 100000
#define EE 1600000
#define INCH 128
#define HID 64
#define OUTC 40

// ---------------- scratch (device globals; no allocation allowed) ----------------
__device__ int   g_cnt[NN];
__device__ int   g_offs[NN + 1];
__device__ int   g_cursor[NN];
__device__ int   g_adj[EE];
__device__ float g_dinv[NN];
__device__ float g_xw[(size_t)NN * HID];   // x @ W1
__device__ float g_h1[(size_t)NN * HID];   // relu(agg1)
__device__ float g_h2[(size_t)NN * OUTC];  // h1 @ W2
__device__ int   g_bsum[128];
__device__ int   g_bscan[128];
__device__ int   g_is64;

// ---------------- edge dtype sniffing (int64 vs int32) ----------------
__global__ void detect_kernel(const void* ei) {
    const unsigned int* w = (const unsigned int*)ei;
    int is64 = 1;
    for (int i = 0; i < 64; i++) {
        if (w[2 * i + 1] != 0u) { is64 = 0; break; }
    }
    g_is64 = is64;
}

__device__ __forceinline__ int edge_row(const void* ei, int e, int is64) {
    if (is64) return (int)((const long long*)ei)[e];
    return ((const int*)ei)[e];
}
__device__ __forceinline__ int edge_col(const void* ei, int e, int is64) {
    if (is64) return (int)((const long long*)ei)[EE + e];
    return ((const int*)ei)[EE + e];
}

// ---------------- CSR build ----------------
__global__ void zero_cnt_kernel() {
    int i = blockIdx.x * blockDim.x + threadIdx.x;
    if (i < NN) g_cnt[i] = 0;
}

__global__ void hist_kernel(const void* __restrict__ ei) {
    int is64 = g_is64;
    for (int e = blockIdx.x * blockDim.x + threadIdx.x; e < EE; e += gridDim.x * blockDim.x) {
        int c = edge_col(ei, e, is64);
        atomicAdd(&g_cnt[c], 1);
    }
}

__global__ void scan_blocks_kernel() {
    __shared__ int sh[1024];
    int tid = threadIdx.x;
    int idx = blockIdx.x * 1024 + tid;
    int v = (idx < NN) ? g_cnt[idx] : 0;
    sh[tid] = v;
    __syncthreads();
    for (int off = 1; off < 1024; off <<= 1) {
        int t = 0;
        if (tid >= off) t = sh[tid - off];
        __syncthreads();
        sh[tid] += t;
        __syncthreads();
    }
    int incl = sh[tid];
    if (idx < NN) g_offs[idx] = incl - v;  // exclusive within block
    if (tid == 1023) g_bsum[blockIdx.x] = incl;
}

__global__ void scan_sums_kernel(int nblocks) {
    __shared__ int sh[128];
    int tid = threadIdx.x;
    int v = (tid < nblocks) ? g_bsum[tid] : 0;
    sh[tid] = v;
    __syncthreads();
    for (int off = 1; off < 128; off <<= 1) {
        int t = 0;
        if (tid >= off) t = sh[tid - off];
        __syncthreads();
        sh[tid] += t;
        __syncthreads();
    }
    if (tid < nblocks) g_bscan[tid] = sh[tid] - v;  // exclusive
}

__global__ void scan_add_kernel() {
    int i = blockIdx.x * blockDim.x + threadIdx.x;
    if (i < NN) {
        int off = g_offs[i] + g_bscan[i >> 10];
        g_offs[i] = off;
        g_cursor[i] = off;
        g_dinv[i] = rsqrtf((float)(g_cnt[i] + 1));  // +1 self-loop
        if (i == NN - 1) g_offs[NN] = off + g_cnt[i];
    }
}

__global__ void scatter_kernel(const void* __restrict__ ei) {
    int is64 = g_is64;
    for (int e = blockIdx.x * blockDim.x + threadIdx.x; e < EE; e += gridDim.x * blockDim.x) {
        int r = edge_row(ei, e, is64);
        int c = edge_col(ei, e, is64);
        int p = atomicAdd(&g_cursor[c], 1);
        g_adj[p] = r;
    }
}

// ---------------- GEMM1: g_xw[N,64] = x[N,128] @ W1[128,64] ----------------
// Block: 128 rows x 64 cols, 128 threads, each thread 8x8 register tile.
#define G1_SMEM ((128 * 64 + 128 * 132) * 4)

__global__ __launch_bounds__(128, 2) void gemm1_kernel(const float* __restrict__ A,
                                                       const float* __restrict__ W) {
    extern __shared__ float smem[];
    float* Ws = smem;               // [128][64]
    float* Xs = smem + 128 * 64;    // [128][132] padded
    int tid = threadIdx.x;
    int m0 = blockIdx.x * 128;
    int valid = NN - m0;

    // load W1 fully: 8192 floats = 2048 float4 / 128 threads = 16 each
    const float4* W4 = (const float4*)W;
    float4* Ws4 = (float4*)Ws;
#pragma unroll
    for (int i = 0; i < 16; i++) Ws4[tid + i * 128] = W4[tid + i * 128];

    // load X tile: 128 rows x 32 float4 = 4096 float4 / 128 = 32 each
#pragma unroll
    for (int j = 0; j < 32; j++) {
        int i = tid + j * 128;
        int row = i >> 5, k4 = i & 31;
        float4 v = make_float4(0.f, 0.f, 0.f, 0.f);
        if (row < valid) v = ((const float4*)A)[(size_t)(m0 + row) * 32 + k4];
        *(float4*)&Xs[row * 132 + k4 * 4] = v;
    }
    __syncthreads();

    int ty = tid >> 3, tx = tid & 7;
    int r0 = ty * 8, c0 = tx * 8;
    float acc[8][8];
#pragma unroll
    for (int i = 0; i < 8; i++)
#pragma unroll
        for (int j = 0; j < 8; j++) acc[i][j] = 0.f;

    for (int k = 0; k < 128; k += 4) {
        float4 a4[8];
#pragma unroll
        for (int i = 0; i < 8; i++) a4[i] = *(const float4*)&Xs[(r0 + i) * 132 + k];
#pragma unroll
        for (int kk = 0; kk < 4; kk++) {
            float4 b0 = *(const float4*)&Ws[(k + kk) * 64 + c0];
            float4 b1 = *(const float4*)&Ws[(k + kk) * 64 + c0 + 4];
            float bv[8] = {b0.x, b0.y, b0.z, b0.w, b1.x, b1.y, b1.z, b1.w};
#pragma unroll
            for (int i = 0; i < 8; i++) {
                float av = ((const float*)&a4[i])[kk];
#pragma unroll
                for (int j = 0; j < 8; j++) acc[i][j] = fmaf(av, bv[j], acc[i][j]);
            }
        }
    }

#pragma unroll
    for (int i = 0; i < 8; i++) {
        int row = m0 + r0 + i;
        if (row < NN) {
            float4 q0 = make_float4(acc[i][0], acc[i][1], acc[i][2], acc[i][3]);
            float4 q1 = make_float4(acc[i][4], acc[i][5], acc[i][6], acc[i][7]);
            *(float4*)&g_xw[(size_t)row * 64 + c0] = q0;
            *(float4*)&g_xw[(size_t)row * 64 + c0 + 4] = q1;
        }
    }
}

// ---------------- agg1: h1 = relu(dinv[c]*(sum dinv[r]*xw[r] + dinv[c]*xw[c]) + b1) ----------------
// 16 lanes per node, each lane one float4 (4 channels of 64).
__global__ void agg1_kernel(const float* __restrict__ b1) {
    int gid = blockIdx.x * blockDim.x + threadIdx.x;
    int node = gid >> 4;
    int lane = gid & 15;
    if (node >= NN) return;
    const float4* xw4 = (const float4*)g_xw;
    float di = g_dinv[node];
    float4 v = __ldg(&xw4[(size_t)node * 16 + lane]);
    float4 acc = make_float4(di * v.x, di * v.y, di * v.z, di * v.w);
    int s = g_offs[node], e = g_offs[node + 1];
    for (int k = s; k < e; k++) {
        int r = __ldg(&g_adj[k]);
        float w = __ldg(&g_dinv[r]);
        float4 u = __ldg(&xw4[(size_t)r * 16 + lane]);
        acc.x = fmaf(w, u.x, acc.x);
        acc.y = fmaf(w, u.y, acc.y);
        acc.z = fmaf(w, u.z, acc.z);
        acc.w = fmaf(w, u.w, acc.w);
    }
    float4 bb = __ldg(&((const float4*)b1)[lane]);
    float4 o;
    o.x = fmaxf(fmaf(di, acc.x, bb.x), 0.f);
    o.y = fmaxf(fmaf(di, acc.y, bb.y), 0.f);
    o.z = fmaxf(fmaf(di, acc.z, bb.z), 0.f);
    o.w = fmaxf(fmaf(di, acc.w, bb.w), 0.f);
    ((float4*)g_h1)[(size_t)node * 16 + lane] = o;
}

// ---------------- GEMM2: g_h2[N,40] = h1[N,64] @ W2[64,40] ----------------
__global__ __launch_bounds__(128, 2) void gemm2_kernel(const float* __restrict__ W) {
    __shared__ float Ws[64 * 40];     // 10240 B
    __shared__ float Xs[128 * 68];    // 34816 B
    int tid = threadIdx.x;
    int m0 = blockIdx.x * 128;
    int valid = NN - m0;

    // W2: 2560 floats = 640 float4 / 128 = 5 each
    const float4* W4 = (const float4*)W;
    float4* Ws4 = (float4*)Ws;
#pragma unroll
    for (int i = 0; i < 5; i++) Ws4[tid + i * 128] = W4[tid + i * 128];

    // X tile: 128 rows x 16 float4 = 2048 float4 / 128 = 16 each
#pragma unroll
    for (int j = 0; j < 16; j++) {
        int i = tid + j * 128;
        int row = i >> 4, k4 = i & 15;
        float4 v = make_float4(0.f, 0.f, 0.f, 0.f);
        if (row < valid) v = ((const float4*)g_h1)[(size_t)(m0 + row) * 16 + k4];
        *(float4*)&Xs[row * 68 + k4 * 4] = v;
    }
    __syncthreads();

    int ty = tid >> 3, tx = tid & 7;
    int r0 = ty * 8, c0 = tx * 5;
    float acc[8][5];
#pragma unroll
    for (int i = 0; i < 8; i++)
#pragma unroll
        for (int j = 0; j < 5; j++) acc[i][j] = 0.f;

    for (int k = 0; k < 64; k += 4) {
        float4 a4[8];
#pragma unroll
        for (int i = 0; i < 8; i++) a4[i] = *(const float4*)&Xs[(r0 + i) * 68 + k];
#pragma unroll
        for (int kk = 0; kk < 4; kk++) {
            float bv[5];
#pragma unroll
            for (int j = 0; j < 5; j++) bv[j] = Ws[(k + kk) * 40 + c0 + j];
#pragma unroll
            for (int i = 0; i < 8; i++) {
                float av = ((const float*)&a4[i])[kk];
#pragma unroll
                for (int j = 0; j < 5; j++) acc[i][j] = fmaf(av, bv[j], acc[i][j]);
            }
        }
    }

#pragma unroll
    for (int i = 0; i < 8; i++) {
        int row = m0 + r0 + i;
        if (row < NN) {
#pragma unroll
            for (int j = 0; j < 5; j++) g_h2[(size_t)row * 40 + c0 + j] = acc[i][j];
        }
    }
}

// ---------------- agg2: out = dinv[c]*(sum dinv[r]*h2[r] + dinv[c]*h2[c]) + b2 ----------------
// 10 lanes per node (3 nodes per warp, lanes 30,31 idle), each lane one float4 (4 of 40 ch).
__global__ void agg2_kernel(const float* __restrict__ b2, float* __restrict__ out) {
    int gtid = blockIdx.x * blockDim.x + threadIdx.x;
    int wid = gtid >> 5;
    int lane = gtid & 31;
    int g = lane / 10;
    int sub = lane % 10;
    if (g >= 3) return;
    int node = wid * 3 + g;
    if (node >= NN) return;
    const float4* h4 = (const float4*)g_h2;
    float di = g_dinv[node];
    float4 v = __ldg(&h4[(size_t)node * 10 + sub]);
    float4 acc = make_float4(di * v.x, di * v.y, di * v.z, di * v.w);
    int s = g_offs[node], e = g_offs[node + 1];
    for (int k = s; k < e; k++) {
        int r = __ldg(&g_adj[k]);
        float w = __ldg(&g_dinv[r]);
        float4 u = __ldg(&h4[(size_t)r * 10 + sub]);
        acc.x = fmaf(w, u.x, acc.x);
        acc.y = fmaf(w, u.y, acc.y);
        acc.z = fmaf(w, u.z, acc.z);
        acc.w = fmaf(w, u.w, acc.w);
    }
    float4 bb = __ldg(&((const float4*)b2)[sub]);
    float4 o;
    o.x = fmaf(di, acc.x, bb.x);
    o.y = fmaf(di, acc.y, bb.y);
    o.z = fmaf(di, acc.z, bb.z);
    o.w = fmaf(di, acc.w, bb.w);
    ((float4*)out)[(size_t)node * 10 + sub] = o;
}

// ---------------- launch ----------------
extern "C" void kernel_launch(void* const* d_in, const int* in_sizes, int n_in,
                              void* d_out, int out_size) {
    const float* x  = (const float*)d_in[0];
    const void*  ei = d_in[1];
    const float* W1 = (const float*)d_in[2];
    const float* b1 = (const float*)d_in[3];
    const float* W2 = (const float*)d_in[4];
    const float* b2 = (const float*)d_in[5];
    float* out = (float*)d_out;

    const int nscanblocks = (NN + 1023) / 1024;  // 98

    detect_kernel<<<1, 1>>>(ei);
    zero_cnt_kernel<<<(NN + 255) / 256, 256>>>();
    hist_kernel<<<2048, 256>>>(ei);
    scan_blocks_kernel<<<nscanblocks, 1024>>>();
    scan_sums_kernel<<<1, 128>>>(nscanblocks);
    scan_add_kernel<<<(NN + 255) / 256, 256>>>();
    scatter_kernel<<<2048, 256>>>(ei);

    cudaFuncSetAttribute(gemm1_kernel, cudaFuncAttributeMaxDynamicSharedMemorySize, G1_SMEM);
    gemm1_kernel<<<(NN + 127) / 128, 128, G1_SMEM>>>(x, W1);
    agg1_kernel<<<(NN * 16 + 255) / 256, 256>>>(b1);
    gemm2_kernel<<<(NN + 127) / 128, 128>>>(W2);
    agg2_kernel<<<(NN + 23) / 24 , 256>>>(b2, out);
}